// round 14
// baseline (speedup 1.0000x reference)
#include <cuda_runtime.h>
#include <cuda_fp16.h>
#include <cstdint>

// Problem constants (fixed by setup_inputs): B=8, C=1, H=352, W=1216, times=24
#define Bn 8
#define Hn 352
#define Wn 1216
#define HW (Hn * Wn)            // 428032
#define BHW (Bn * HW)           // 3424256
#define TIMES 24

// Padded feature layout: stride 1248, 16 guard cols each side, 1 guard row.
#define PSTR 1248
#define PIMG ((Hn + 2) * PSTR)
#define COFF 16

// Static device scratch (allocation-free).
// Weights: 8 x u8 per pixel (tap order, center skipped) against a per-pixel
// half scale (= max_w/255). Masked (measured) px: u=0, scale=0 -> out = fc.
// g_affu2: uint2 per px, interleaved by vertical pixel pair -> one aligned
//   uint4 per column per 2 rows: uint4 index = b*HW/2 + (y>>1)*Wn + x.
// g_scl: half per px, interleaved by vertical quad: (b*HW/4+(y>>2)*Wn+x)*4+(y&3).
__device__ uint2  g_affu2[BHW];
__device__ __half g_scl[BHW];
__device__ float  g_feat0[(size_t)Bn * PIMG];
__device__ float  g_feat1[(size_t)Bn * PIMG];

// ---------------------------------------------------------------------------
// Zero only the guard cells of both padded buffers (interior is overwritten).
// ---------------------------------------------------------------------------
__global__ void guard_zero_kernel()
{
    const int i = blockIdx.x * 256 + threadIdx.x;
    const int nTB = Bn * 2 * PSTR;                    // top+bottom full rows
    if (i < nTB) {
        const int img = i / (2 * PSTR);
        const int r   = (i / PSTR) & 1;
        const int c   = i % PSTR;
        const size_t off = (size_t)img * PIMG + (size_t)(r ? (Hn + 1) : 0) * PSTR + c;
        g_feat0[off] = 0.0f;
        g_feat1[off] = 0.0f;
    }
    const int j = i - nTB;
    if (j >= 0 && j < Bn * Hn * 32) {                 // 16 left + 16 right guard cols
        const int img = j / (Hn * 32);
        const int rem = j % (Hn * 32);
        const int r   = rem / 32;
        const int c   = rem % 32;
        const int col = (c < 16) ? c : (COFF + Wn + (c - 16));
        const size_t off = (size_t)img * PIMG + (size_t)(r + 1) * PSTR + col;
        g_feat0[off] = 0.0f;
        g_feat1[off] = 0.0f;
    }
}

// ---------------------------------------------------------------------------
// Quantize one pixel's 9 |aff| taps -> packed u8 uint2 + half scale.
// Identical arithmetic/order to previous rounds (rel_err preserved).
// ---------------------------------------------------------------------------
__device__ __forceinline__ void quant_px(const float a[9], bool m,
                                         uint2& pv, __half& hs)
{
    float s = 0.0f;
#pragma unroll
    for (int k = 0; k < 9; ++k) s += a[k];
    const float inv = m ? 0.0f : (1.0f / s);
    float w[8];
    w[0] = a[0] * inv; w[1] = a[1] * inv; w[2] = a[2] * inv; w[3] = a[3] * inv;
    w[4] = a[5] * inv; w[5] = a[6] * inv; w[6] = a[7] * inv; w[7] = a[8] * inv;

    float wmax = w[0];
#pragma unroll
    for (int k = 1; k < 8; ++k) wmax = fmaxf(wmax, w[k]);

    const float q = (wmax > 0.0f) ? (255.0f / wmax) : 0.0f;
    unsigned u[8];
#pragma unroll
    for (int k = 0; k < 8; ++k)
        u[k] = (unsigned)__float2int_rn(w[k] * q);

    pv.x = u[0] | (u[1] << 8) | (u[2] << 16) | (u[3] << 24);
    pv.y = u[4] | (u[5] << 8) | (u[6] << 16) | (u[7] << 24);
    hs = __float2half(wmax * (1.0f / 255.0f));
}

// ---------------------------------------------------------------------------
// Prep v2: thread = (x, 4 consecutive rows). All loads coalesced scalars;
// all stores coalesced (2x uint4 aff pairs, 1x uint2 scales, 4 feat floats).
// ---------------------------------------------------------------------------
__global__ void __launch_bounds__(256)
prep_kernel(const float* __restrict__ aff,
            const float* __restrict__ feature,
            const float* __restrict__ sparse)
{
    const int x  = blockIdx.x * 32 + threadIdx.x;         // 38*32 = 1216
    const int y0 = (blockIdx.y * 8 + threadIdx.y) * 4;    // 11*8*4 = 352
    const int b  = blockIdx.z;

    uint2  pv[4];
    __half hs[4];

#pragma unroll
    for (int r = 0; r < 4; ++r) {
        const int y = y0 + r;
        const size_t hw = (size_t)y * Wn + x;
        const float* ap = aff + (size_t)b * 9 * HW + hw;
        float a[9];
#pragma unroll
        for (int k = 0; k < 9; ++k)
            a[k] = fabsf(__ldg(ap + (size_t)k * HW));

        const size_t idx = (size_t)b * HW + hw;
        const float sd = __ldg(sparse + idx);
        const bool  m  = sd > 0.0f;
        quant_px(a, m, pv[r], hs[r]);

        const float ft = __ldg(feature + idx);
        g_feat0[(size_t)b * PIMG + (size_t)(y + 1) * PSTR + (x + COFF)] =
            m ? sd : ft;
    }

    // Pair-interleaved aff: uint4 {rows y0,y0+1} and {rows y0+2,y0+3}.
    const size_t p0 = (size_t)b * (HW / 2) + (size_t)(y0 >> 1) * Wn + x;
    uint4* affv = reinterpret_cast<uint4*>(g_affu2);
    affv[p0]      = make_uint4(pv[0].x, pv[0].y, pv[1].x, pv[1].y);
    affv[p0 + Wn] = make_uint4(pv[2].x, pv[2].y, pv[3].x, pv[3].y);

    // Quad-interleaved scales: one uint2 = 4 halves for rows y0..y0+3.
    const size_t q0 = (size_t)b * (HW / 4) + (size_t)(y0 >> 2) * Wn + x;
    __half2 h01 = __halves2half2(hs[0], hs[1]);
    __half2 h23 = __halves2half2(hs[2], hs[3]);
    uint2 sv;
    sv.x = *reinterpret_cast<unsigned*>(&h01);
    sv.y = *reinterpret_cast<unsigned*>(&h23);
    reinterpret_cast<uint2*>(g_scl)[q0] = sv;
}

// ---------------------------------------------------------------------------
// One Jacobi step for one pixel: out = fc + scale * sum_k u_k * (n_k - fc).
// Tap order: (-1,-1)(-1,0)(-1,+1)(0,-1)(0,+1)(+1,-1)(+1,0)(+1,+1).
// ---------------------------------------------------------------------------
__device__ __forceinline__ float prop(unsigned Ax, unsigned Ay, float sc, float fc,
                                      float n0, float n1, float n2,
                                      float n3, float n5,
                                      float n6, float n7, float n8)
{
    float acc;
    acc = (float)(Ax & 0xFFu) * (n0 - fc);
    acc = fmaf((float)((Ax >> 8)  & 0xFFu), n1 - fc, acc);
    acc = fmaf((float)((Ax >> 16) & 0xFFu), n2 - fc, acc);
    acc = fmaf((float)((Ax >> 24)        ), n3 - fc, acc);
    acc = fmaf((float)(Ay & 0xFFu),          n5 - fc, acc);
    acc = fmaf((float)((Ay >> 8)  & 0xFFu), n6 - fc, acc);
    acc = fmaf((float)((Ay >> 16) & 0xFFu), n7 - fc, acc);
    acc = fmaf((float)((Ay >> 24)        ), n8 - fc, acc);
    return fmaf(sc, acc, fc);
}

// ---------------------------------------------------------------------------
// Propagation step, 2 columns x 4 rows (8 px) per thread (unchanged R13).
// ---------------------------------------------------------------------------
__global__ void __launch_bounds__(256)
step_kernel(const float* __restrict__ fin,
            float* __restrict__ fout,
            int lastFlag)
{
    const int x0 = (blockIdx.x * 32 + threadIdx.x) * 2;     // 19*32*2 = 1216
    const int y0 = (blockIdx.y * 8 + threadIdx.y) * 4;      // 11*8*4 = 352
    const int b  = blockIdx.z;
    const size_t pb = (size_t)b * PIMG + (size_t)(y0 + 1) * PSTR + (x0 + COFF);

    // rows y0-1 .. y0+4: center float2 + left/right edge scalars
    float2 C[6];
    float  L[6], R[6];
#pragma unroll
    for (int j = 0; j < 6; ++j) {
        const size_t ro = pb + (size_t)(j - 1) * PSTR;
        C[j] = __ldg(reinterpret_cast<const float2*>(fin + ro));
        L[j] = __ldg(fin + ro - 1);
        R[j] = __ldg(fin + ro + 2);
    }

    const size_t p0 = (size_t)b * (HW / 2) + (size_t)(y0 >> 1) * Wn + x0;
    const uint4* affv = reinterpret_cast<const uint4*>(g_affu2);
    const uint4 A00 = __ldg(affv + p0);               // col0, rows y0,y0+1
    const uint4 A01 = __ldg(affv + p0 + 1);           // col1, rows y0,y0+1
    const uint4 A10 = __ldg(affv + p0 + Wn);          // col0, rows y0+2,y0+3
    const uint4 A11 = __ldg(affv + p0 + Wn + 1);      // col1, rows y0+2,y0+3

    const size_t q0 = (size_t)b * (HW / 4) + (size_t)(y0 >> 2) * Wn + x0;
    const uint4 SS = __ldg(reinterpret_cast<const uint4*>(
        reinterpret_cast<const uint2*>(g_scl) + q0));
    const float2 sc0a = __half22float2(*reinterpret_cast<const __half2*>(&SS.x));
    const float2 sc0b = __half22float2(*reinterpret_cast<const __half2*>(&SS.y));
    const float2 sc1a = __half22float2(*reinterpret_cast<const __half2*>(&SS.z));
    const float2 sc1b = __half22float2(*reinterpret_cast<const __half2*>(&SS.w));

    float2 o[4];
    o[0].x = prop(A00.x, A00.y, sc0a.x, C[1].x, L[0], C[0].x, C[0].y, L[1], C[1].y, L[2], C[2].x, C[2].y);
    o[0].y = prop(A01.x, A01.y, sc1a.x, C[1].y, C[0].x, C[0].y, R[0], C[1].x, R[1], C[2].x, C[2].y, R[2]);
    o[1].x = prop(A00.z, A00.w, sc0a.y, C[2].x, L[1], C[1].x, C[1].y, L[2], C[2].y, L[3], C[3].x, C[3].y);
    o[1].y = prop(A01.z, A01.w, sc1a.y, C[2].y, C[1].x, C[1].y, R[1], C[2].x, R[2], C[3].x, C[3].y, R[3]);
    o[2].x = prop(A10.x, A10.y, sc0b.x, C[3].x, L[2], C[2].x, C[2].y, L[3], C[3].y, L[4], C[4].x, C[4].y);
    o[2].y = prop(A11.x, A11.y, sc1b.x, C[3].y, C[2].x, C[2].y, R[2], C[3].x, R[3], C[4].x, C[4].y, R[4]);
    o[3].x = prop(A10.z, A10.w, sc0b.y, C[4].x, L[3], C[3].x, C[3].y, L[4], C[4].y, L[5], C[5].x, C[5].y);
    o[3].y = prop(A11.z, A11.w, sc1b.y, C[4].y, C[3].x, C[3].y, R[3], C[4].x, R[4], C[5].x, C[5].y, R[5]);

    if (lastFlag) {
        float* ob = fout + (size_t)b * HW + (size_t)y0 * Wn + x0;
#pragma unroll
        for (int j = 0; j < 4; ++j)
            *reinterpret_cast<float2*>(ob + (size_t)j * Wn) = o[j];
    } else {
#pragma unroll
        for (int j = 0; j < 4; ++j)
            *reinterpret_cast<float2*>(fout + pb + (size_t)j * PSTR) = o[j];
    }
}

// ---------------------------------------------------------------------------
extern "C" void kernel_launch(void* const* d_in, const int* in_sizes, int n_in,
                              void* d_out, int out_size)
{
    const float* aff     = (const float*)d_in[0];
    const float* feature = (const float*)d_in[1];
    const float* sparse  = (const float*)d_in[2];
    float* out = (float*)d_out;

    float* f0 = nullptr;
    float* f1 = nullptr;
    cudaGetSymbolAddress((void**)&f0, g_feat0);
    cudaGetSymbolAddress((void**)&f1, g_feat1);

    const dim3 blkStep(32, 8);
    const dim3 grdPrep(38, 11, Bn);                 // 38*32 = 1216, 11*8*4 = 352
    const dim3 grdStep(19, 11, Bn);                 // 19*32*2 = 1216, 11*8*4 = 352

    guard_zero_kernel<<<512, 256>>>();
    prep_kernel<<<grdPrep, blkStep>>>(aff, feature, sparse);

    for (int t = 0; t < TIMES; ++t) {
        const float* fin = (t & 1) ? f1 : f0;
        if (t == TIMES - 1) {
            step_kernel<<<grdStep, blkStep>>>(fin, out, 1);
        } else {
            float* fo = (t & 1) ? f0 : f1;
            step_kernel<<<grdStep, blkStep>>>(fin, fo, 0);
        }
    }
}

// round 15
// speedup vs baseline: 1.2234x; 1.2234x over previous
#include <cuda_runtime.h>
#include <cuda_fp16.h>
#include <cstdint>

// Problem constants (fixed by setup_inputs): B=8, C=1, H=352, W=1216, times=24
#define Bn 8
#define Hn 352
#define Wn 1216
#define HW (Hn * Wn)            // 428032
#define BHW (Bn * HW)           // 3424256
#define TIMES 24
#define NGROUPS 2               // two independent batch chains (4 images each)
#define BG (Bn / NGROUPS)

// Padded feature layout: stride 1248, 16 guard cols each side, 1 guard row.
#define PSTR 1248
#define PIMG ((Hn + 2) * PSTR)
#define COFF 16

// Static device scratch (allocation-free).
// Weights: 8 x u8 per pixel (tap order, center skipped) against a per-pixel
// half scale (= max_w/255). Masked (measured) px: u=0, scale=0 -> out = fc.
// g_affu2: uint2 per px, interleaved by vertical pixel pair -> one aligned
//   uint4 per column per 2 rows: uint4 index = b*HW/2 + (y>>1)*Wn + x.
// g_scl: half per px, interleaved by vertical quad: (b*HW/4+(y>>2)*Wn+x)*4+(y&3).
__device__ uint2  g_affu2[BHW];
__device__ __half g_scl[BHW];
__device__ float  g_feat0[(size_t)Bn * PIMG];
__device__ float  g_feat1[(size_t)Bn * PIMG];

// ---------------------------------------------------------------------------
// Zero only the guard cells of both padded buffers (interior is overwritten).
// ---------------------------------------------------------------------------
__global__ void guard_zero_kernel()
{
    const int i = blockIdx.x * 256 + threadIdx.x;
    const int nTB = Bn * 2 * PSTR;                    // top+bottom full rows
    if (i < nTB) {
        const int img = i / (2 * PSTR);
        const int r   = (i / PSTR) & 1;
        const int c   = i % PSTR;
        const size_t off = (size_t)img * PIMG + (size_t)(r ? (Hn + 1) : 0) * PSTR + c;
        g_feat0[off] = 0.0f;
        g_feat1[off] = 0.0f;
    }
    const int j = i - nTB;
    if (j >= 0 && j < Bn * Hn * 32) {                 // 16 left + 16 right guard cols
        const int img = j / (Hn * 32);
        const int rem = j % (Hn * 32);
        const int r   = rem / 32;
        const int c   = rem % 32;
        const int col = (c < 16) ? c : (COFF + Wn + (c - 16));
        const size_t off = (size_t)img * PIMG + (size_t)(r + 1) * PSTR + col;
        g_feat0[off] = 0.0f;
        g_feat1[off] = 0.0f;
    }
}

// ---------------------------------------------------------------------------
// Prep (R13 version: 4 px/thread horizontally, float4 input loads):
// normalize |affinity|; quantize 8 non-center weights to u8 + per-pixel scale
// (pair/quad-interleaved layouts); build initial padded feature.
// ---------------------------------------------------------------------------
__global__ void __launch_bounds__(256)
prep_kernel(const float* __restrict__ aff,
            const float* __restrict__ feature,
            const float* __restrict__ sparse)
{
    const int x0 = (blockIdx.x * 16 + threadIdx.x) * 4;   // W = 19*16*4 exact
    const int y  = blockIdx.y * 16 + threadIdx.y;         // H = 22*16 exact
    const int b  = blockIdx.z;
    const int hw = y * Wn + x0;
    const size_t idx = (size_t)b * HW + hw;

    const float* ap = aff + (size_t)b * 9 * HW + hw;
    float4 a[9];
#pragma unroll
    for (int k = 0; k < 9; ++k)
        a[k] = __ldg(reinterpret_cast<const float4*>(ap + (size_t)k * HW));

    float4 s = make_float4(0.f, 0.f, 0.f, 0.f);
#pragma unroll
    for (int k = 0; k < 9; ++k) {
        a[k].x = fabsf(a[k].x); a[k].y = fabsf(a[k].y);
        a[k].z = fabsf(a[k].z); a[k].w = fabsf(a[k].w);
        s.x += a[k].x; s.y += a[k].y; s.z += a[k].z; s.w += a[k].w;
    }

    const float4 sd = __ldg(reinterpret_cast<const float4*>(sparse + idx));
    const float4 ft = __ldg(reinterpret_cast<const float4*>(feature + idx));

    const float sdv[4] = {sd.x, sd.y, sd.z, sd.w};
    const float ftv[4] = {ft.x, ft.y, ft.z, ft.w};
    const float sv[4]  = {s.x, s.y, s.z, s.w};
    float outf[4];

#pragma unroll
    for (int j = 0; j < 4; ++j) {
        const bool  m   = sdv[j] > 0.0f;
        const float inv = m ? 0.0f : (1.0f / sv[j]);
        float w[8];
        w[0] = ((const float*)&a[0])[j] * inv;
        w[1] = ((const float*)&a[1])[j] * inv;
        w[2] = ((const float*)&a[2])[j] * inv;
        w[3] = ((const float*)&a[3])[j] * inv;
        w[4] = ((const float*)&a[5])[j] * inv;
        w[5] = ((const float*)&a[6])[j] * inv;
        w[6] = ((const float*)&a[7])[j] * inv;
        w[7] = ((const float*)&a[8])[j] * inv;

        float wmax = w[0];
#pragma unroll
        for (int k = 1; k < 8; ++k) wmax = fmaxf(wmax, w[k]);

        const float q = (wmax > 0.0f) ? (255.0f / wmax) : 0.0f;
        unsigned u[8];
#pragma unroll
        for (int k = 0; k < 8; ++k)
            u[k] = (unsigned)__float2int_rn(w[k] * q);

        uint2 pv;
        pv.x = u[0] | (u[1] << 8) | (u[2] << 16) | (u[3] << 24);
        pv.y = u[4] | (u[5] << 8) | (u[6] << 16) | (u[7] << 24);

        const int xx = x0 + j;
        const size_t pairIdx = (size_t)b * (HW / 2) + (size_t)(y >> 1) * Wn + xx;
        g_affu2[pairIdx * 2 + (y & 1)] = pv;
        const size_t qIdx = (size_t)b * (HW / 4) + (size_t)(y >> 2) * Wn + xx;
        g_scl[qIdx * 4 + (y & 3)] = __float2half(wmax * (1.0f / 255.0f));

        outf[j] = m ? sdv[j] : ftv[j];
    }

    const size_t pidx = (size_t)b * PIMG + (size_t)(y + 1) * PSTR + (x0 + COFF);
    *reinterpret_cast<float4*>(&g_feat0[pidx]) =
        make_float4(outf[0], outf[1], outf[2], outf[3]);
}

// ---------------------------------------------------------------------------
// One Jacobi step for one pixel: out = fc + scale * sum_k u_k * (n_k - fc).
// Tap order: (-1,-1)(-1,0)(-1,+1)(0,-1)(0,+1)(+1,-1)(+1,0)(+1,+1).
// ---------------------------------------------------------------------------
__device__ __forceinline__ float prop(unsigned Ax, unsigned Ay, float sc, float fc,
                                      float n0, float n1, float n2,
                                      float n3, float n5,
                                      float n6, float n7, float n8)
{
    float acc;
    acc = (float)(Ax & 0xFFu) * (n0 - fc);
    acc = fmaf((float)((Ax >> 8)  & 0xFFu), n1 - fc, acc);
    acc = fmaf((float)((Ax >> 16) & 0xFFu), n2 - fc, acc);
    acc = fmaf((float)((Ax >> 24)        ), n3 - fc, acc);
    acc = fmaf((float)(Ay & 0xFFu),          n5 - fc, acc);
    acc = fmaf((float)((Ay >> 8)  & 0xFFu), n6 - fc, acc);
    acc = fmaf((float)((Ay >> 16) & 0xFFu), n7 - fc, acc);
    acc = fmaf((float)((Ay >> 24)        ), n8 - fc, acc);
    return fmaf(sc, acc, fc);
}

// ---------------------------------------------------------------------------
// Propagation step, 2 columns x 4 rows (8 px) per thread (R13), per-group.
// ---------------------------------------------------------------------------
__global__ void __launch_bounds__(256)
step_kernel(const float* __restrict__ fin,
            float* __restrict__ fout,
            int bBase, int lastFlag)
{
    const int x0 = (blockIdx.x * 32 + threadIdx.x) * 2;     // 19*32*2 = 1216
    const int y0 = (blockIdx.y * 8 + threadIdx.y) * 4;      // 11*8*4 = 352
    const int b  = bBase + blockIdx.z;
    const size_t pb = (size_t)b * PIMG + (size_t)(y0 + 1) * PSTR + (x0 + COFF);

    // rows y0-1 .. y0+4: center float2 + left/right edge scalars
    float2 C[6];
    float  L[6], R[6];
#pragma unroll
    for (int j = 0; j < 6; ++j) {
        const size_t ro = pb + (size_t)(j - 1) * PSTR;
        C[j] = __ldg(reinterpret_cast<const float2*>(fin + ro));
        L[j] = __ldg(fin + ro - 1);
        R[j] = __ldg(fin + ro + 2);
    }

    const size_t p0 = (size_t)b * (HW / 2) + (size_t)(y0 >> 1) * Wn + x0;
    const uint4* affv = reinterpret_cast<const uint4*>(g_affu2);
    const uint4 A00 = __ldg(affv + p0);               // col0, rows y0,y0+1
    const uint4 A01 = __ldg(affv + p0 + 1);           // col1, rows y0,y0+1
    const uint4 A10 = __ldg(affv + p0 + Wn);          // col0, rows y0+2,y0+3
    const uint4 A11 = __ldg(affv + p0 + Wn + 1);      // col1, rows y0+2,y0+3

    const size_t q0 = (size_t)b * (HW / 4) + (size_t)(y0 >> 2) * Wn + x0;
    const uint4 SS = __ldg(reinterpret_cast<const uint4*>(
        reinterpret_cast<const uint2*>(g_scl) + q0));
    const float2 sc0a = __half22float2(*reinterpret_cast<const __half2*>(&SS.x));
    const float2 sc0b = __half22float2(*reinterpret_cast<const __half2*>(&SS.y));
    const float2 sc1a = __half22float2(*reinterpret_cast<const __half2*>(&SS.z));
    const float2 sc1b = __half22float2(*reinterpret_cast<const __half2*>(&SS.w));

    float2 o[4];
    o[0].x = prop(A00.x, A00.y, sc0a.x, C[1].x, L[0], C[0].x, C[0].y, L[1], C[1].y, L[2], C[2].x, C[2].y);
    o[0].y = prop(A01.x, A01.y, sc1a.x, C[1].y, C[0].x, C[0].y, R[0], C[1].x, R[1], C[2].x, C[2].y, R[2]);
    o[1].x = prop(A00.z, A00.w, sc0a.y, C[2].x, L[1], C[1].x, C[1].y, L[2], C[2].y, L[3], C[3].x, C[3].y);
    o[1].y = prop(A01.z, A01.w, sc1a.y, C[2].y, C[1].x, C[1].y, R[1], C[2].x, R[2], C[3].x, C[3].y, R[3]);
    o[2].x = prop(A10.x, A10.y, sc0b.x, C[3].x, L[2], C[2].x, C[2].y, L[3], C[3].y, L[4], C[4].x, C[4].y);
    o[2].y = prop(A11.x, A11.y, sc1b.x, C[3].y, C[2].x, C[2].y, R[2], C[3].x, R[3], C[4].x, C[4].y, R[4]);
    o[3].x = prop(A10.z, A10.w, sc0b.y, C[4].x, L[3], C[3].x, C[3].y, L[4], C[4].y, L[5], C[5].x, C[5].y);
    o[3].y = prop(A11.z, A11.w, sc1b.y, C[4].y, C[3].x, C[3].y, R[3], C[4].x, R[4], C[5].x, C[5].y, R[5]);

    if (lastFlag) {
        float* ob = fout + (size_t)b * HW + (size_t)y0 * Wn + x0;
#pragma unroll
        for (int j = 0; j < 4; ++j)
            *reinterpret_cast<float2*>(ob + (size_t)j * Wn) = o[j];
    } else {
#pragma unroll
        for (int j = 0; j < 4; ++j)
            *reinterpret_cast<float2*>(fout + pb + (size_t)j * PSTR) = o[j];
    }
}

// ---------------------------------------------------------------------------
// Two independent per-group chains on two streams (graph fork/join): each
// group's launch gaps and wave tails are filled by the other group's work.
// ---------------------------------------------------------------------------
extern "C" void kernel_launch(void* const* d_in, const int* in_sizes, int n_in,
                              void* d_out, int out_size)
{
    const float* aff     = (const float*)d_in[0];
    const float* feature = (const float*)d_in[1];
    const float* sparse  = (const float*)d_in[2];
    float* out = (float*)d_out;

    float* f0 = nullptr;
    float* f1 = nullptr;
    cudaGetSymbolAddress((void**)&f0, g_feat0);
    cudaGetSymbolAddress((void**)&f1, g_feat1);

    // One-time host-side infra (no device memory involved).
    static cudaStream_t s1 = nullptr;
    static cudaEvent_t evFork = nullptr, evJoin = nullptr;
    if (s1 == nullptr) {
        cudaStreamCreateWithFlags(&s1, cudaStreamNonBlocking);
        cudaEventCreateWithFlags(&evFork, cudaEventDisableTiming);
        cudaEventCreateWithFlags(&evJoin, cudaEventDisableTiming);
    }

    const dim3 blkPrep(16, 16);
    const dim3 grdPrep(19, 22, Bn);                 // 19*16*4 = 1216, 22*16 = 352
    const dim3 blkStep(32, 8);
    const dim3 grdStep(19, 11, BG);                 // per-group: 836 blocks

    guard_zero_kernel<<<512, 256>>>();
    prep_kernel<<<grdPrep, blkPrep>>>(aff, feature, sparse);

    // Fork: group 1 chain runs on s1, group 0 chain on the capture stream.
    cudaEventRecord(evFork, 0);
    cudaStreamWaitEvent(s1, evFork, 0);

    for (int t = 0; t < TIMES; ++t) {
        const float* fin = (t & 1) ? f1 : f0;
        const int last = (t == TIMES - 1);
        float* fo = last ? out : ((t & 1) ? f0 : f1);
        step_kernel<<<grdStep, blkStep, 0, 0 >>>(fin, fo, 0,  last);
        step_kernel<<<grdStep, blkStep, 0, s1>>>(fin, fo, BG, last);
    }

    // Join: capture stream waits for group 1 chain.
    cudaEventRecord(evJoin, s1);
    cudaStreamWaitEvent(0, evJoin, 0);
}